// round 15
// baseline (speedup 1.0000x reference)
#include <cuda_runtime.h>

// CostVolume3D: B=8, H=128, W=256, C=8, D=23.
// Group-serial, fully-unrolled 23-iter loop (rL starts at 0 for every group:
// compile-time L-phase schedule), closed-form tap segment order, segment-sum.
// NEW: each thread interleaves TWO independent groups (m, m+TPB) to provide a
// second dependency chain — the R14 profile showed issue=57.5% latency-bound.
// Stores staged via stride-23 smem (conflict-free), coalesced float4 out.

#define W_ 256
#define D_ 23
static constexpr int NF  = 8 * 128 * 256 * 8;    // 2,097,152
static constexpr int NW  = 8 * 128 * 256;        // 262,144 groups
static constexpr int TPB = 128;
static constexpr int GPB = 2 * TPB;              // groups per block
static constexpr unsigned LASTF = (unsigned)(NF - 1);

struct GState {
    int   w2v, base, s, x0v, iW, iA;
    float w, frac, fm1, r0f, W0, W1, W2, A0, A1, dA;
    float* sb;
};

static __device__ __forceinline__ void tap_init(
    const float* __restrict__ fr, GState& g, int w2v_in)
{
    const float disp = g.w - (float)(g.s - 11);
    const float xq   = (float)w2v_in - disp;
    const float x0f  = floorf(xq);
    g.frac = xq - x0f;
    g.fm1  = g.frac - 1.0f;
    g.x0v  = (int)x0f;
    const int x0i = min(max(g.x0v, 0), W_ - 1);
    const unsigned p0 = (unsigned)(g.base + x0i) * 8u;
    const unsigned i0 = p0 / 23u;
    g.r0f = (float)(int)(p0 - i0 * 23u);
    g.iW  = (int)i0;
    g.W0 = __ldg(fr + g.iW);
    g.W1 = __ldg(fr + min((unsigned)g.iW + 1u, LASTF));
    g.W2 = __ldg(fr + min((unsigned)g.iW + 2u, LASTF));
}

static __device__ __forceinline__ void group_init(
    const float* __restrict__ fl, const float* __restrict__ fr,
    const float* __restrict__ wf, int m, float* sb, GState& g)
{
    const int q0 = m * 23;
    g.w    = __ldg(wf + m);
    g.w2v  = q0 & (W_ - 1);
    g.base = q0 - g.w2v;
    const int x = q0 >> 15;
    g.s = x - 23 * ((x * 179) >> 12);            // x % 23 (x < 184)
    g.iA = m * 8;                                // rL starts at 0
    g.A0 = __ldg(fl + g.iA);
    g.A1 = __ldg(fl + g.iA + 1);
    g.dA = g.A1 - g.A0;
    g.sb = sb;
    tap_init(fr, g, g.w2v);
}

template <int J>
static __device__ __forceinline__ void step(
    const float* __restrict__ fl, const float* __restrict__ fr, GState& g)
{
    // rL_j = (8j)%23 ; tL_j = min(23-rL_j, 8); L-window advance when rL_j>=15
    constexpr int  RL  = (8 * J) % 23;
    constexpr float TL = (23 - RL < 8) ? (float)(23 - RL) : 8.0f;
    constexpr bool ADV = (RL >= 15) && (J != 22);
    constexpr int  ANX = (8 * J) / 23 + 2;       // next A1 offset from iA

    if (g.w2v == W_) {                           // rare: row crossing
        g.w2v = 0; g.base += W_;
        if ((g.base & 32767) == 0) g.s = (g.s == 22) ? 0 : g.s + 1;
        tap_init(fr, g, 0);
    }

    const bool  e   = (g.x0v < W_ - 1);
    const bool  hi0 = (g.r0f >= 15.0f);
    const float t23 = 23.0f - g.r0f;
    const float u = hi0 ? t23 : (e ? fminf(15.0f - g.r0f, 8.0f) : 8.0f);
    const float v = (!e && hi0) ? t23 : 8.0f;

    const float dW01 = g.W1 - g.W0;
    const float dW12 = g.W2 - g.W1;
    const bool  inc  = e && hi0;
    const float D0 = g.fm1 * dW01;
    const float D1 = -g.frac * (inc ? dW12 : dW01);
    const float du = hi0 ? D0 : D1;
    const float dv = hi0 ? D1 : D0;
    const float be = g.A0 - g.W0;
    const float e0 = inc ? fmaf(-g.frac, dW01, be) : be;

    float acc;
    if (TL >= 8.0f) {                            // no L-flip: 3 segments
        const float g1 = e0 + du;
        const float g2 = g1 + dv;
        acc = u * fabsf(e0);
        acc = fmaf(v - u,    fabsf(g1), acc);
        acc = fmaf(8.0f - v, fabsf(g2), acc);
    } else {
        const float a = fminf(TL, u);
        const float c = fmaxf(TL, v);
        const float b = ((TL + u) + v) - (a + c);
        const float g3 = e0 + (g.dA + (du + dv));
        const float g1 = e0 + ((u <= TL) ? du : g.dA);
        const float g2 = g3 - ((v <= TL) ? g.dA : dv);
        acc = a * fabsf(e0);
        acc = fmaf(b - a,    fabsf(g1), acc);
        acc = fmaf(c - b,    fabsf(g2), acc);
        acc = fmaf(8.0f - c, fabsf(g3), acc);
    }
    g.sb[J] = acc;                               // stride-23: conflict-free

    // advance tap stream
    const float nr0 = hi0 ? (g.r0f - 15.0f) : (g.r0f + 8.0f);
    g.x0v += 1;
    if ((unsigned)(g.x0v - 1) < (unsigned)(W_ - 1)) {
        g.r0f = nr0;
        if (hi0) {
            g.iW += 1;
            g.W0 = g.W1; g.W1 = g.W2;
            g.W2 = __ldg(fr + min((unsigned)g.iW + 2u, LASTF));
        }
    }
    g.w2v += 1;

    // advance L window (compile-time schedule)
    if (ADV) {
        g.A0 = g.A1;
        g.A1 = __ldg(fl + min((unsigned)(g.iA + ANX), LASTF));
        g.dA = g.A1 - g.A0;
    }
}

__global__ void __launch_bounds__(TPB)
costvol3d_kernel(const float* __restrict__ fl,
                 const float* __restrict__ fr,
                 const float* __restrict__ wf,
                 float* __restrict__ out)
{
    __shared__ float sbuf[GPB * D_];
    const int tid = threadIdx.x;
    const int M0  = blockIdx.x * GPB;

    GState ga, gb;
    group_init(fl, fr, wf, M0 + tid,       sbuf + tid * D_,             ga);
    group_init(fl, fr, wf, M0 + TPB + tid, sbuf + (TPB + tid) * D_,     gb);

    // Interleave the two independent chains, fully unrolled.
    #define STEP2(J) step<J>(fl, fr, ga); step<J>(fl, fr, gb);
    STEP2(0)  STEP2(1)  STEP2(2)  STEP2(3)  STEP2(4)  STEP2(5)
    STEP2(6)  STEP2(7)  STEP2(8)  STEP2(9)  STEP2(10) STEP2(11)
    STEP2(12) STEP2(13) STEP2(14) STEP2(15) STEP2(16) STEP2(17)
    STEP2(18) STEP2(19) STEP2(20) STEP2(21) STEP2(22)
    #undef STEP2

    __syncthreads();

    // coalesced writeout: block owns out[M0*23 .. M0*23 + GPB*23)
    const float4* s4 = reinterpret_cast<const float4*>(sbuf);
    float4* o4 = reinterpret_cast<float4*>(out + M0 * D_);
    constexpr int NV4 = GPB * D_ / 4;            // 1472
#pragma unroll
    for (int i = 0; i < NV4 / TPB + 1; i++) {
        const int idx = i * TPB + tid;
        if (idx < NV4) o4[idx] = s4[idx];
    }
}

extern "C" void kernel_launch(void* const* d_in, const int* in_sizes, int n_in,
                              void* d_out, int out_size)
{
    const float* feat_l = (const float*)d_in[0];
    const float* feat_r = (const float*)d_in[1];
    const float* wflow  = (const float*)d_in[2];
    float* out = (float*)d_out;

    costvol3d_kernel<<<NW / GPB, TPB>>>(feat_l, feat_r, wflow, out);
}

// round 16
// speedup vs baseline: 1.1156x; 1.1156x over previous
#include <cuda_runtime.h>

// CostVolume3D: B=8, H=128, W=256, C=8, D=23.
// Half-group per thread: group m's 23 outputs split j=0..11 / j=12..22 across
// two threads (warp-uniform halves, no divergence). Doubles warp count
// (occupancy was the R15 binding constraint) and halves the serial chain.
// L-stream phase is compile-time per half (rL(j)=(8j)%23; at j=12 rL=4,
// A-index 8m+4). Closed-form tap segment order; segment-sum; stride-23 smem
// staging; coalesced float4 writeout.

#define W_ 256
#define D_ 23
static constexpr int NF  = 8 * 128 * 256 * 8;    // 2,097,152
static constexpr int NW  = 8 * 128 * 256;        // 262,144 groups
static constexpr int TPB = 256;
static constexpr int GPB = 128;                  // groups per block
static constexpr unsigned LASTF = (unsigned)(NF - 1);

struct GState {
    int   w2v, base, s, x0v, iW, iA;
    float w, frac, fm1, r0f, W0, W1, W2, A0, A1, dA;
};

static __device__ __forceinline__ void tap_init(
    const float* __restrict__ fr, GState& g, int w2v_in)
{
    const float disp = g.w - (float)(g.s - 11);
    const float xq   = (float)w2v_in - disp;
    const float x0f  = floorf(xq);
    g.frac = xq - x0f;
    g.fm1  = g.frac - 1.0f;
    g.x0v  = (int)x0f;
    const int x0i = min(max(g.x0v, 0), W_ - 1);
    const unsigned p0 = (unsigned)(g.base + x0i) * 8u;
    const unsigned i0 = p0 / 23u;
    g.r0f = (float)(int)(p0 - i0 * 23u);
    g.iW  = (int)i0;
    g.W0 = __ldg(fr + g.iW);
    g.W1 = __ldg(fr + min((unsigned)g.iW + 1u, LASTF));
    g.W2 = __ldg(fr + min((unsigned)g.iW + 2u, LASTF));
}

template <int J0>
static __device__ __forceinline__ void group_init(
    const float* __restrict__ fl, const float* __restrict__ fr,
    const float* __restrict__ wf, int m, GState& g)
{
    constexpr int KJ = (8 * J0) / 23;            // A-window offset at J0
    const int qs = m * 23 + J0;
    g.w    = __ldg(wf + m);
    g.w2v  = qs & (W_ - 1);
    g.base = qs - g.w2v;
    const int x = qs >> 15;
    g.s = x - 23 * ((x * 179) >> 12);            // x % 23 (x < 184)
    g.iA = m * 8;
    g.A0 = __ldg(fl + g.iA + KJ);
    g.A1 = __ldg(fl + g.iA + KJ + 1);            // <= 8m+5: in bounds
    g.dA = g.A1 - g.A0;
    tap_init(fr, g, g.w2v);
}

template <int J, int JLAST>
static __device__ __forceinline__ void step(
    const float* __restrict__ fl, const float* __restrict__ fr,
    GState& g, float* __restrict__ sb)
{
    constexpr int   RL = (8 * J) % 23;
    constexpr float TL = (23 - RL < 8) ? (float)(23 - RL) : 8.0f;
    constexpr bool ADV = (RL >= 15) && (J != JLAST);
    constexpr int  ANX = (8 * J) / 23 + 2;

    if (g.w2v == W_) {                           // rare: row crossing
        g.w2v = 0; g.base += W_;
        if ((g.base & 32767) == 0) g.s = (g.s == 22) ? 0 : g.s + 1;
        tap_init(fr, g, 0);
    }

    const bool  e   = (g.x0v < W_ - 1);
    const bool  hi0 = (g.r0f >= 15.0f);
    const float t23 = 23.0f - g.r0f;
    const float u = hi0 ? t23 : (e ? fminf(15.0f - g.r0f, 8.0f) : 8.0f);
    const float v = (!e && hi0) ? t23 : 8.0f;

    const float dW01 = g.W1 - g.W0;
    const float dW12 = g.W2 - g.W1;
    const bool  inc  = e && hi0;
    const float D0 = g.fm1 * dW01;
    const float D1 = -g.frac * (inc ? dW12 : dW01);
    const float du = hi0 ? D0 : D1;
    const float dv = hi0 ? D1 : D0;
    const float be = g.A0 - g.W0;
    const float e0 = inc ? fmaf(-g.frac, dW01, be) : be;

    float acc;
    if (TL >= 8.0f) {                            // no L-flip: 3 segments
        const float g1 = e0 + du;
        const float g2 = g1 + dv;
        acc = u * fabsf(e0);
        acc = fmaf(v - u,    fabsf(g1), acc);
        acc = fmaf(8.0f - v, fabsf(g2), acc);
    } else {
        const float a = fminf(TL, u);
        const float c = fmaxf(TL, v);
        const float b = ((TL + u) + v) - (a + c);
        const float g3 = e0 + (g.dA + (du + dv));
        const float g1 = e0 + ((u <= TL) ? du : g.dA);
        const float g2 = g3 - ((v <= TL) ? g.dA : dv);
        acc = a * fabsf(e0);
        acc = fmaf(b - a,    fabsf(g1), acc);
        acc = fmaf(c - b,    fabsf(g2), acc);
        acc = fmaf(8.0f - c, fabsf(g3), acc);
    }
    sb[J] = acc;                                 // stride-23: conflict-free

    // advance tap stream
    const float nr0 = hi0 ? (g.r0f - 15.0f) : (g.r0f + 8.0f);
    g.x0v += 1;
    if ((unsigned)(g.x0v - 1) < (unsigned)(W_ - 1)) {
        g.r0f = nr0;
        if (hi0) {
            g.iW += 1;
            g.W0 = g.W1; g.W1 = g.W2;
            g.W2 = __ldg(fr + min((unsigned)g.iW + 2u, LASTF));
        }
    }
    g.w2v += 1;

    // advance L window (compile-time schedule)
    if (ADV) {
        g.A0 = g.A1;
        g.A1 = __ldg(fl + min((unsigned)(g.iA + ANX), LASTF));
        g.dA = g.A1 - g.A0;
    }
}

template <int J, int JEND>
static __device__ __forceinline__ void run_steps(
    const float* __restrict__ fl, const float* __restrict__ fr,
    GState& g, float* __restrict__ sb)
{
    if constexpr (J < JEND) {
        step<J, JEND - 1>(fl, fr, g, sb);
        run_steps<J + 1, JEND>(fl, fr, g, sb);
    }
}

__global__ void __launch_bounds__(TPB)
costvol3d_kernel(const float* __restrict__ fl,
                 const float* __restrict__ fr,
                 const float* __restrict__ wf,
                 float* __restrict__ out)
{
    __shared__ float sbuf[GPB * D_];
    const int tid = threadIdx.x;
    const int M0  = blockIdx.x * GPB;

    // warps 0-3: first halves (j=0..11); warps 4-7: second halves (j=12..22)
    const int gg = tid & (GPB - 1);
    const int m  = M0 + gg;
    float* sb = sbuf + gg * D_;

    GState g;
    if (tid < GPB) {
        group_init<0>(fl, fr, wf, m, g);
        run_steps<0, 12>(fl, fr, g, sb);
    } else {
        group_init<12>(fl, fr, wf, m, g);
        run_steps<12, 23>(fl, fr, g, sb);
    }

    __syncthreads();

    // coalesced writeout: block owns out[M0*23 .. +GPB*23)
    const float4* s4 = reinterpret_cast<const float4*>(sbuf);
    float4* o4 = reinterpret_cast<float4*>(out + M0 * D_);
    constexpr int NV4 = GPB * D_ / 4;            // 736
#pragma unroll
    for (int i = 0; i < (NV4 + TPB - 1) / TPB; i++) {
        const int idx = i * TPB + tid;
        if (idx < NV4) o4[idx] = s4[idx];
    }
}

extern "C" void kernel_launch(void* const* d_in, const int* in_sizes, int n_in,
                              void* d_out, int out_size)
{
    const float* feat_l = (const float*)d_in[0];
    const float* feat_r = (const float*)d_in[1];
    const float* wflow  = (const float*)d_in[2];
    float* out = (float*)d_out;

    costvol3d_kernel<<<NW / GPB, TPB>>>(feat_l, feat_r, wflow, out);
}